// round 11
// baseline (speedup 1.0000x reference)
#include <cuda_runtime.h>
#include <cuda_fp16.h>
#include <cstdint>

// Problem constants (fixed by setup_inputs)
#define BB 8
#define TT 4096
#define II 1024
#define HH 1024
#define MTOT (BB * TT)          // 32768
#define NC 32                   // scan chunks
#define CL 128                  // chunk length (NC*CL == TT)

#define KC 128                  // K-chunk (two 64-col SW128 sub-tiles per tensor)
#define NCHUNK (II / KC)        // 8
#define SUB_BYTES (128 * 128)   // 128 rows x 128B = 16KB sub-tile
#define STAGE_BYTES (6 * SUB_BYTES)    // x0,x1,wz0,wz1,wh0,wh1 = 96KB
#define SMEM_TOTAL (2 * STAGE_BYTES)   // 192KB
#define NTILES 2048             // (MTOT/128) * (HH/128)
#define GRID_GEMM 148

// ---------------- scratch (device globals; no allocation allowed) ----------------
__device__ float g_a[(size_t)MTOT * HH];   // a_t = sigmoid(-k)
__device__ float g_b[(size_t)MTOT * HH];   // b_t = sigmoid(k)*g(p)
__device__ float g_A [BB * NC * HH];
__device__ float g_Bc[BB * NC * HH];
__device__ float g_carry[BB * NC * HH];
__device__ __half g_x16[(size_t)MTOT * II];
__device__ __half g_wz[HH * II];
__device__ __half g_wh[HH * II];

// ---------------- helpers ----------------
__device__ __forceinline__ uint32_t smem_u32(const void* p) {
    uint32_t a;
    asm("{ .reg .u64 t; cvta.to.shared.u64 t, %1; cvt.u32.u64 %0, t; }" : "=r"(a) : "l"(p));
    return a;
}
__device__ __forceinline__ void cp16(uint32_t saddr, const void* gaddr) {
    asm volatile("cp.async.cg.shared.global [%0], [%1], 16;" :: "r"(saddr), "l"(gaddr));
}
__device__ __forceinline__ void cp_commit() { asm volatile("cp.async.commit_group;" ::: "memory"); }
template <int N>
__device__ __forceinline__ void cp_wait() { asm volatile("cp.async.wait_group %0;" :: "n"(N) : "memory"); }

__device__ __forceinline__ void ldsm4(uint32_t (&r)[4], uint32_t addr) {
    asm volatile("ldmatrix.sync.aligned.m8n8.x4.shared.b16 {%0,%1,%2,%3}, [%4];"
        : "=r"(r[0]), "=r"(r[1]), "=r"(r[2]), "=r"(r[3]) : "r"(addr));
}
#define MMA16816(d, a, b0v, b1v) \
    asm volatile("mma.sync.aligned.m16n8k16.row.col.f32.f16.f16.f32 " \
        "{%0,%1,%2,%3}, {%4,%5,%6,%7}, {%8,%9}, {%0,%1,%2,%3};" \
        : "+f"((d)[0]), "+f"((d)[1]), "+f"((d)[2]), "+f"((d)[3]) \
        : "r"((a)[0]), "r"((a)[1]), "r"((a)[2]), "r"((a)[3]), "r"(b0v), "r"(b1v))

__device__ __forceinline__ uint32_t sw128(uint32_t off) { return off ^ ((off >> 3) & 0x70); }

// ---- pure fixed-latency-pipe exp / rcp (keep MUFU idle) ----
__device__ __forceinline__ float fexp(float x) {           // e^x, rel err ~2e-7
    float t = x * 1.4426950408889634f;
    float fi = t + 12582912.0f;
    int i = __float_as_int(fi) - 0x4B400000;
    float f = t - (fi - 12582912.0f);
    float p = 1.5403530393381609e-4f;
    p = fmaf(p, f, 1.3333558146428443e-3f);
    p = fmaf(p, f, 9.6181291076284772e-3f);
    p = fmaf(p, f, 5.5504108664821580e-2f);
    p = fmaf(p, f, 2.4022650695910072e-1f);
    p = fmaf(p, f, 6.9314718055994531e-1f);
    p = fmaf(p, f, 1.0f);
    return __int_as_float(__float_as_int(p) + (i << 23));
}
__device__ __forceinline__ float frcp(float d) {           // 1/d, d>0 normal
    float y = __int_as_float(0x7EF311C3 - __float_as_int(d));
    y = y * (2.0f - d * y);
    y = y * (2.0f - d * y);
    y = y * (2.0f - d * y);
    return y;
}
__device__ __forceinline__ float g_fn_scan(float x) {
    return (x >= 0.0f) ? (x + 0.5f) : frcp(1.0f + fexp(-x));
}

// ---------------- convert fp32 -> fp16 ----------------
__global__ __launch_bounds__(256)
void cvt_kernel(const float* __restrict__ in, __half* __restrict__ out) {
    size_t i = ((size_t)blockIdx.x * blockDim.x + threadIdx.x) * 4;
    float4 v = *(const float4*)(in + i);
    *(__half2*)(out + i)     = __half2(__float2half(v.x), __float2half(v.y));
    *(__half2*)(out + i + 2) = __half2(__float2half(v.z), __float2half(v.w));
}

// ---------------- chunk loader: 6 sub-tiles (x/wz/wh x 2 k-halves), SW128 ----------------
__device__ __forceinline__ void load_chunk(uint32_t sbase, int m0, int n0, int k0, int tid) {
#pragma unroll
    for (int t = 0; t < 3; ++t) {
        const __half* base;
        int r0;
        if      (t == 0) { base = g_x16; r0 = m0; }
        else if (t == 1) { base = g_wz;  r0 = n0; }
        else             { base = g_wh;  r0 = n0; }
#pragma unroll
        for (int half = 0; half < 2; ++half) {
            uint32_t sub = sbase + (uint32_t)(t * 2 + half) * (uint32_t)SUB_BYTES;
            int kk = k0 + half * 64;
#pragma unroll
            for (int s = 0; s < 4; ++s) {
                int i = tid + s * 256;        // 1024 chunks: 128 rows x 8 x 16B
                int r = i >> 3;
                int u = i & 7;
                const char* gp = (const char*)(base + (size_t)(r0 + r) * II + kk) + u * 16;
                uint32_t off = (uint32_t)(r * 128 + u * 16);
                cp16(sub + sw128(off), gp);
            }
        }
    }
}

// ---------------- persistent dual GEMM + fused chunk-summary epilogue ----------------
__global__ __launch_bounds__(256, 1)
void gemm_mma_kernel(const float* __restrict__ bz, const float* __restrict__ bh) {
    extern __shared__ char smem[];
    const uint32_t sb = smem_u32(smem);
    const int tid = threadIdx.x;
    const int lane = tid & 31;
    const int wid = tid >> 5;
    const int g = lane >> 3, lr = lane & 7;
    const int wm = (wid >> 1) * 32;     // 4 warps along M
    const int wn = (wid & 1) * 64;      // 2 warps along N
    const int G = gridDim.x;

    // prologue: first tile's chunk 0
    {
        int t0 = blockIdx.x;
        load_chunk(sb, (t0 >> 3) * 128, (t0 & 7) * 128, 0, tid);
        cp_commit();
    }
    int slot = 0;

    for (int t = blockIdx.x; t < NTILES; t += G) {
        const int m0 = (t >> 3) * 128;
        const int n0 = (t & 7) * 128;

        float acck[2][8][4], accp[2][8][4];
#pragma unroll
        for (int mt = 0; mt < 2; ++mt)
#pragma unroll
            for (int nt = 0; nt < 8; ++nt)
#pragma unroll
                for (int q = 0; q < 4; ++q) { acck[mt][nt][q] = 0.0f; accp[mt][nt][q] = 0.0f; }

        for (int c = 0; c < NCHUNK; ++c) {
            cp_wait<0>();          // chunk c resident in `slot`
            __syncthreads();       // all warps done with other slot (MMA or epilogue)
            if (c + 1 < NCHUNK) {
                load_chunk(sb + (uint32_t)(slot ^ 1) * STAGE_BYTES, m0, n0, (c + 1) * KC, tid);
                cp_commit();
            } else {
                int tn = t + G;
                if (tn < NTILES) {
                    load_chunk(sb + (uint32_t)(slot ^ 1) * STAGE_BYTES, (tn >> 3) * 128, (tn & 7) * 128, 0, tid);
                    cp_commit();
                }
            }

            const uint32_t st = sb + (uint32_t)slot * STAGE_BYTES;
#pragma unroll
            for (int ks = 0; ks < 8; ++ks) {
                const int half = ks >> 2, ksl = ks & 3;
                const uint32_t sA = st + (uint32_t)(0 + half) * SUB_BYTES;
                const uint32_t sZ = st + (uint32_t)(2 + half) * SUB_BYTES;
                const uint32_t sH = st + (uint32_t)(4 + half) * SUB_BYTES;

                uint32_t af[2][4];
#pragma unroll
                for (int mt = 0; mt < 2; ++mt) {
                    uint32_t off = sw128((uint32_t)((wm + mt * 16 + (g & 1) * 8 + lr) * 128 + (2 * ksl + (g >> 1)) * 16));
                    ldsm4(af[mt], sA + off);
                }
                uint32_t bzf[4][4], bhf[4][4];
#pragma unroll
                for (int j = 0; j < 4; ++j) {
                    uint32_t off = sw128((uint32_t)((wn + j * 16 + (g >> 1) * 8 + lr) * 128 + (2 * ksl + (g & 1)) * 16));
                    ldsm4(bzf[j], sZ + off);
                    ldsm4(bhf[j], sH + off);
                }
#pragma unroll
                for (int mt = 0; mt < 2; ++mt)
#pragma unroll
                    for (int nt = 0; nt < 8; ++nt) {
                        int j = nt >> 1, h = (nt & 1) * 2;
                        MMA16816(acck[mt][nt], af[mt], bzf[j][h], bzf[j][h + 1]);
                        MMA16816(accp[mt][nt], af[mt], bhf[j][h], bhf[j][h + 1]);
                    }
            }
            slot ^= 1;
        }

        // ---- epilogue in the dead slot (slot^1); next tile's chunk 0 loads into `slot` ----
        __syncthreads();   // all warps done reading dead slot
        float* planeA = (float*)(smem + (size_t)(slot ^ 1) * STAGE_BYTES);   // 64 x 132
        float* planeB = planeA + 64 * 132;
        float* partA  = planeB + 64 * 132;   // 512
        float* partB  = partA + 512;         // 512

#pragma unroll
        for (int ph = 0; ph < 2; ++ph) {
            // phase ph: rows ph*64 .. ph*64+63 (owned by warps wid/2 == ph*2, ph*2+1)
            if ((wid >> 2) == ph) {
#pragma unroll
                for (int mt = 0; mt < 2; ++mt)
#pragma unroll
                    for (int nt = 0; nt < 8; ++nt) {
                        int cc = wn + nt * 8 + (lane & 3) * 2;
                        float bzv0 = bz[n0 + cc], bzv1 = bz[n0 + cc + 1];
                        float bhv0 = bh[n0 + cc], bhv1 = bh[n0 + cc + 1];
#pragma unroll
                        for (int h = 0; h < 2; ++h) {
                            int r = (wm & 63) + mt * 16 + (lane >> 2) + h * 8;   // local 0..63
                            float kv0 = acck[mt][nt][2 * h]     + bzv0;
                            float kv1 = acck[mt][nt][2 * h + 1] + bzv1;
                            float pv0 = accp[mt][nt][2 * h]     + bhv0;
                            float pv1 = accp[mt][nt][2 * h + 1] + bhv1;

                            float e0 = fexp(kv0), e1 = fexp(kv1);
                            float r0 = frcp(1.0f + e0), r1 = frcp(1.0f + e1);
                            float z0 = e0 * r0, z1 = e1 * r1;       // sigmoid(k)
                            float em0 = fexp(-pv0), em1 = fexp(-pv1);
                            float gs0 = frcp(1.0f + em0), gs1 = frcp(1.0f + em1);
                            float gg0 = (pv0 >= 0.0f) ? (pv0 + 0.5f) : gs0;
                            float gg1 = (pv1 >= 0.0f) ? (pv1 + 0.5f) : gs1;

                            *(float2*)(planeA + r * 132 + cc) = make_float2(r0, r1);
                            *(float2*)(planeB + r * 132 + cc) = make_float2(z0 * gg0, z1 * gg1);
                        }
                    }
            }
            __syncthreads();

            // segment summaries: 256 threads = 2 segments x 128 h, 32 steps each
            {
                const int h = tid & 127;
                const int s = tid >> 7;           // segment within half
                float A = 1.0f, Bacc = 0.0f;
                const float* pa = planeA + (s * 32) * 132 + h;
                const float* pb = planeB + (s * 32) * 132 + h;
#pragma unroll 8
                for (int i = 0; i < 32; ++i) {
                    float a = pa[i * 132];
                    float bb = pb[i * 132];
                    Bacc = fmaf(a, Bacc, bb);
                    A *= a;
                }
                partA[ph * 256 + tid] = A;
                partB[ph * 256 + tid] = Bacc;
            }
            // coalesced stores for this half
#pragma unroll
            for (int pass = 0; pass < 2; ++pass) {
                int r = pass * 32 + (tid >> 3);
                size_t grow = (size_t)(m0 + ph * 64 + r) * HH + n0;
#pragma unroll
                for (int q = 0; q < 4; ++q) {
                    int c4 = q * 8 + (tid & 7);
                    *(float4*)(g_a + grow + c4 * 4) = *(float4*)(planeA + r * 132 + c4 * 4);
                    *(float4*)(g_b + grow + c4 * 4) = *(float4*)(planeB + r * 132 + c4 * 4);
                }
            }
            __syncthreads();
        }

        // combine 4 segments (rows 0-31,32-63,64-95,96-127) per h
        if (tid < 128) {
            float A0 = partA[tid],       B0 = partB[tid];
            float A1 = partA[128 + tid], B1 = partB[128 + tid];
            float A2 = partA[256 + tid], B2 = partB[256 + tid];
            float A3 = partA[384 + tid], B3 = partB[384 + tid];
            float b01 = fmaf(A1, B0, B1);
            float b23 = fmaf(A3, B2, B3);
            int b = m0 >> 12, c = (m0 >> 7) & (NC - 1);
            int idx = (b * NC + c) * HH + n0 + tid;
            g_A[idx]  = (A0 * A1) * (A2 * A3);
            g_Bc[idx] = fmaf(A2 * A3, b01, b23);
        }
        // next iteration's c=0 __syncthreads() protects the dead slot from the next prefetch
    }
}

// ---------------- scan pass 2: combine chunks ----------------
__global__ __launch_bounds__(256)
void scan_chunk_combine(const float* __restrict__ h0) {
    int idx = blockIdx.x * blockDim.x + threadIdx.x;   // (b, h)
    int h = idx & (HH - 1);
    int b = idx >> 10;
    float carry = g_fn_scan(h0[b * HH + h]);
#pragma unroll
    for (int c = 0; c < NC; ++c) {
        int s = (b * NC + c) * HH + h;
        g_carry[s] = carry;
        carry = fmaf(g_A[s], carry, g_Bc[s]);
    }
}

// ---------------- scan pass 3: apply carries, write output ----------------
__global__ __launch_bounds__(256)
void scan_apply(float* __restrict__ out) {
    int idx = blockIdx.x * blockDim.x + threadIdx.x;   // (b, c, h)
    int h = idx & (HH - 1);
    int c = (idx >> 10) & (NC - 1);
    int b = idx >> 15;
    size_t base = ((size_t)(b * TT + c * CL)) * HH + h;
    float hc = g_carry[(b * NC + c) * HH + h];
#pragma unroll 8
    for (int i = 0; i < CL; ++i) {
        float a = g_a[base + (size_t)i * HH];
        float bb = g_b[base + (size_t)i * HH];
        hc = fmaf(a, hc, bb);
        out[base + (size_t)i * HH] = hc;
    }
}

extern "C" void kernel_launch(void* const* d_in, const int* in_sizes, int n_in,
                              void* d_out, int out_size) {
    const float* x  = (const float*)d_in[0];
    const float* h0 = (const float*)d_in[1];
    const float* Wz = (const float*)d_in[2];
    const float* bz = (const float*)d_in[3];
    const float* Wh = (const float*)d_in[4];
    const float* bh = (const float*)d_in[5];
    float* out = (float*)d_out;

    __half *x16, *wz, *wh;
    cudaGetSymbolAddress((void**)&x16, g_x16);
    cudaGetSymbolAddress((void**)&wz,  g_wz);
    cudaGetSymbolAddress((void**)&wh,  g_wh);

    cvt_kernel<<<(int)(((size_t)MTOT * II) / 1024), 256>>>(x, x16);
    cvt_kernel<<<(HH * II) / 1024, 256>>>(Wz, wz);
    cvt_kernel<<<(HH * II) / 1024, 256>>>(Wh, wh);

    cudaFuncSetAttribute(gemm_mma_kernel, cudaFuncAttributeMaxDynamicSharedMemorySize, SMEM_TOTAL);
    gemm_mma_kernel<<<GRID_GEMM, 256, SMEM_TOTAL>>>(bz, bh);

    scan_chunk_combine<<<(BB * HH) / 256, 256>>>(h0);
    scan_apply<<<(BB * NC * HH) / 256, 256>>>(out);
}

// round 13
// speedup vs baseline: 1.1591x; 1.1591x over previous
#include <cuda_runtime.h>
#include <cuda_fp16.h>
#include <cstdint>

// Problem constants (fixed by setup_inputs)
#define BB 8
#define TT 4096
#define II 1024
#define HH 1024
#define MTOT (BB * TT)          // 32768
#define NC 32                   // scan chunks
#define CL 128                  // chunk length (NC*CL == TT)

#define KC 64                   // K-chunk (64 fp16 = 128B rows, SW128 swizzle)
#define NCHUNK (II / KC)        // 16
#define X_BYTES (128 * 128)     // x tile: 128 rows x 128B = 16KB
#define W_BYTES (64 * 128)      // W tile: 64 rows x 128B = 8KB
#define STAGE_BYTES (X_BYTES + 2 * W_BYTES)   // 32KB
#define NSTAGE 3
#define SMEM_TOTAL (NSTAGE * STAGE_BYTES)     // 96KB -> 2 CTAs/SM

// ---------------- scratch (device globals; no allocation allowed) ----------------
__device__ float g_a[(size_t)MTOT * HH];   // a_t = sigmoid(-k)
__device__ float g_b[(size_t)MTOT * HH];   // b_t = sigmoid(k)*g(p)
__device__ float g_A [BB * NC * HH];
__device__ float g_Bc[BB * NC * HH];
__device__ float g_carry[BB * NC * HH];
__device__ __half g_x16[(size_t)MTOT * II];
__device__ __half g_wz[HH * II];
__device__ __half g_wh[HH * II];

// ---------------- helpers ----------------
__device__ __forceinline__ uint32_t smem_u32(const void* p) {
    uint32_t a;
    asm("{ .reg .u64 t; cvta.to.shared.u64 t, %1; cvt.u32.u64 %0, t; }" : "=r"(a) : "l"(p));
    return a;
}
__device__ __forceinline__ void cp16(uint32_t saddr, const void* gaddr) {
    asm volatile("cp.async.cg.shared.global [%0], [%1], 16;" :: "r"(saddr), "l"(gaddr));
}
__device__ __forceinline__ void cp_commit() { asm volatile("cp.async.commit_group;" ::: "memory"); }
template <int N>
__device__ __forceinline__ void cp_wait() { asm volatile("cp.async.wait_group %0;" :: "n"(N) : "memory"); }

__device__ __forceinline__ void ldsm4(uint32_t (&r)[4], uint32_t addr) {
    asm volatile("ldmatrix.sync.aligned.m8n8.x4.shared.b16 {%0,%1,%2,%3}, [%4];"
        : "=r"(r[0]), "=r"(r[1]), "=r"(r[2]), "=r"(r[3]) : "r"(addr));
}
#define MMA16816(d, a, b0v, b1v) \
    asm volatile("mma.sync.aligned.m16n8k16.row.col.f32.f16.f16.f32 " \
        "{%0,%1,%2,%3}, {%4,%5,%6,%7}, {%8,%9}, {%0,%1,%2,%3};" \
        : "+f"((d)[0]), "+f"((d)[1]), "+f"((d)[2]), "+f"((d)[3]) \
        : "r"((a)[0]), "r"((a)[1]), "r"((a)[2]), "r"((a)[3]), "r"(b0v), "r"(b1v))

__device__ __forceinline__ uint32_t sw128(uint32_t off) { return off ^ ((off >> 3) & 0x70); }

// ---- pure fixed-latency-pipe exp / rcp (keep MUFU idle) ----
__device__ __forceinline__ float fexp(float x) {           // e^x, rel err ~2e-7
    float t = x * 1.4426950408889634f;
    float fi = t + 12582912.0f;
    int i = __float_as_int(fi) - 0x4B400000;
    float f = t - (fi - 12582912.0f);
    float p = 1.5403530393381609e-4f;
    p = fmaf(p, f, 1.3333558146428443e-3f);
    p = fmaf(p, f, 9.6181291076284772e-3f);
    p = fmaf(p, f, 5.5504108664821580e-2f);
    p = fmaf(p, f, 2.4022650695910072e-1f);
    p = fmaf(p, f, 6.9314718055994531e-1f);
    p = fmaf(p, f, 1.0f);
    return __int_as_float(__float_as_int(p) + (i << 23));
}
__device__ __forceinline__ float frcp(float d) {           // 1/d, d>0 normal
    float y = __int_as_float(0x7EF311C3 - __float_as_int(d));
    y = y * (2.0f - d * y);
    y = y * (2.0f - d * y);
    y = y * (2.0f - d * y);
    return y;
}
__device__ __forceinline__ float g_fn_scan(float x) {
    return (x >= 0.0f) ? (x + 0.5f) : frcp(1.0f + fexp(-x));
}

// ---------------- convert fp32 -> fp16 ----------------
__global__ __launch_bounds__(256)
void cvt_kernel(const float* __restrict__ in, __half* __restrict__ out) {
    size_t i = ((size_t)blockIdx.x * blockDim.x + threadIdx.x) * 4;
    float4 v = *(const float4*)(in + i);
    *(__half2*)(out + i)     = __half2(__float2half(v.x), __float2half(v.y));
    *(__half2*)(out + i + 2) = __half2(__float2half(v.z), __float2half(v.w));
}

// ---------------- chunk loader: x(128x64) + wz(64x64) + wh(64x64), SW128 ----------------
__device__ __forceinline__ void load_chunk(uint32_t sbase, int m0, int n0, int k0, int tid) {
    // x tile: 1024 cp16 ops
#pragma unroll
    for (int s = 0; s < 4; ++s) {
        int i = tid + s * 256;
        int r = i >> 3;
        int u = i & 7;
        const char* gp = (const char*)(g_x16 + (size_t)(m0 + r) * II + k0) + u * 16;
        uint32_t off = (uint32_t)(r * 128 + u * 16);
        cp16(sbase + sw128(off), gp);
    }
    // wz tile: 512 ops
#pragma unroll
    for (int s = 0; s < 2; ++s) {
        int i = tid + s * 256;
        int r = i >> 3;
        int u = i & 7;
        const char* gp = (const char*)(g_wz + (size_t)(n0 + r) * II + k0) + u * 16;
        uint32_t off = (uint32_t)(r * 128 + u * 16);
        cp16(sbase + (uint32_t)X_BYTES + sw128(off), gp);
    }
    // wh tile: 512 ops
#pragma unroll
    for (int s = 0; s < 2; ++s) {
        int i = tid + s * 256;
        int r = i >> 3;
        int u = i & 7;
        const char* gp = (const char*)(g_wh + (size_t)(n0 + r) * II + k0) + u * 16;
        uint32_t off = (uint32_t)(r * 128 + u * 16);
        cp16(sbase + (uint32_t)(X_BYTES + W_BYTES) + sw128(off), gp);
    }
}

// ---------------- dual GEMM via mma.sync, 128x64 tile, 2 CTAs/SM ----------------
__global__ __launch_bounds__(256, 2)
void gemm_mma_kernel(const float* __restrict__ bz, const float* __restrict__ bh) {
    extern __shared__ char smem[];
    const uint32_t sb = smem_u32(smem);
    const int tid = threadIdx.x;
    const int lane = tid & 31;
    const int wid = tid >> 5;
    const int g = lane >> 3, lr = lane & 7;
    const int wm = (wid >> 1) * 32;     // 4 warps along M (32 rows each)
    const int wn = (wid & 1) * 32;      // 2 warps along N (32 cols each)
    const int n0 = blockIdx.x * 64;     // H block (x-fast: wave shares x tiles)
    const int m0 = blockIdx.y * 128;

    float acck[2][4][4], accp[2][4][4];
#pragma unroll
    for (int mt = 0; mt < 2; ++mt)
#pragma unroll
        for (int nt = 0; nt < 4; ++nt)
#pragma unroll
            for (int q = 0; q < 4; ++q) { acck[mt][nt][q] = 0.0f; accp[mt][nt][q] = 0.0f; }

    // legal depth-2 pipeline on 3 buffers: buffers c%3, (c+1)%3 resident/in-flight,
    // prefetch target (c+2)%3 is always distinct from both.
    load_chunk(sb, m0, n0, 0, tid);
    cp_commit();
    load_chunk(sb + STAGE_BYTES, m0, n0, KC, tid);
    cp_commit();

    for (int c = 0; c < NCHUNK; ++c) {
        if (c + 2 < NCHUNK) {
            load_chunk(sb + ((c + 2) % NSTAGE) * STAGE_BYTES, m0, n0, (c + 2) * KC, tid);
            cp_commit();
            cp_wait<2>();    // chunk c's group complete
        } else if (c + 1 < NCHUNK) {
            cp_wait<1>();
        } else {
            cp_wait<0>();
        }
        __syncthreads();

        const uint32_t st = sb + (c % NSTAGE) * STAGE_BYTES;
        const uint32_t sA = st;
        const uint32_t sZ = st + X_BYTES, sH = st + X_BYTES + W_BYTES;

#pragma unroll
        for (int ks = 0; ks < 4; ++ks) {
            uint32_t af[2][4];
#pragma unroll
            for (int mt = 0; mt < 2; ++mt) {
                uint32_t off = sw128((uint32_t)((wm + mt * 16 + (g & 1) * 8 + lr) * 128 + (2 * ks + (g >> 1)) * 16));
                ldsm4(af[mt], sA + off);
            }
            uint32_t bzf[2][4], bhf[2][4];
#pragma unroll
            for (int j = 0; j < 2; ++j) {
                uint32_t off = sw128((uint32_t)((wn + j * 16 + (g >> 1) * 8 + lr) * 128 + (2 * ks + (g & 1)) * 16));
                ldsm4(bzf[j], sZ + off);
                ldsm4(bhf[j], sH + off);
            }
#pragma unroll
            for (int mt = 0; mt < 2; ++mt)
#pragma unroll
                for (int nt = 0; nt < 4; ++nt) {
                    int j = nt >> 1, h = (nt & 1) * 2;
                    MMA16816(acck[mt][nt], af[mt], bzf[j][h], bzf[j][h + 1]);
                    MMA16816(accp[mt][nt], af[mt], bhf[j][h], bhf[j][h + 1]);
                }
        }
        __syncthreads();
    }

    // ---- epilogue: activations -> smem planes [128][68], fused chunk summary ----
    float* planeA = (float*)smem;            // 128*68 floats (34.8KB)
    float* planeB = planeA + 128 * 68;
    float* partA  = planeB + 128 * 68;       // 256
    float* partB  = partA + 256;

#pragma unroll
    for (int mt = 0; mt < 2; ++mt)
#pragma unroll
        for (int nt = 0; nt < 4; ++nt) {
            int cc = wn + nt * 8 + (lane & 3) * 2;
            float bzv0 = bz[n0 + cc], bzv1 = bz[n0 + cc + 1];
            float bhv0 = bh[n0 + cc], bhv1 = bh[n0 + cc + 1];
#pragma unroll
            for (int h = 0; h < 2; ++h) {
                int r = wm + mt * 16 + (lane >> 2) + h * 8;   // local t-row 0..127
                float kv0 = acck[mt][nt][2 * h]     + bzv0;
                float kv1 = acck[mt][nt][2 * h + 1] + bzv1;
                float pv0 = accp[mt][nt][2 * h]     + bhv0;
                float pv1 = accp[mt][nt][2 * h + 1] + bhv1;

                float e0 = fexp(kv0), e1 = fexp(kv1);
                float r0 = frcp(1.0f + e0), r1 = frcp(1.0f + e1);
                float z0 = e0 * r0, z1 = e1 * r1;       // sigmoid(k)
                float em0 = fexp(-pv0), em1 = fexp(-pv1);
                float gs0 = frcp(1.0f + em0), gs1 = frcp(1.0f + em1);
                float gg0 = (pv0 >= 0.0f) ? (pv0 + 0.5f) : gs0;
                float gg1 = (pv1 >= 0.0f) ? (pv1 + 0.5f) : gs1;

                *(float2*)(planeA + r * 68 + cc) = make_float2(r0, r1);
                *(float2*)(planeB + r * 68 + cc) = make_float2(z0 * gg0, z1 * gg1);
            }
        }
    __syncthreads();

    // ---- in-CTA chunk summary: 256 threads = 4 segments x 64 h, 32 steps each ----
    {
        const int h = tid & 63;
        const int s = tid >> 6;              // 0..3 -> rows s*32..s*32+31
        float A = 1.0f, Bacc = 0.0f;
        const float* pa = planeA + (s * 32) * 68 + h;
        const float* pb = planeB + (s * 32) * 68 + h;
#pragma unroll 8
        for (int i = 0; i < 32; ++i) {
            float a = pa[i * 68];
            float bb = pb[i * 68];
            Bacc = fmaf(a, Bacc, bb);
            A *= a;
        }
        partA[tid] = A;
        partB[tid] = Bacc;
    }
    __syncthreads();
    if (tid < 64) {
        float A0 = partA[tid],       B0 = partB[tid];
        float A1 = partA[64 + tid],  B1 = partB[64 + tid];
        float A2 = partA[128 + tid], B2 = partB[128 + tid];
        float A3 = partA[192 + tid], B3 = partB[192 + tid];
        float b01 = fmaf(A1, B0, B1);
        float b23 = fmaf(A3, B2, B3);
        int b = m0 >> 12, c = (m0 >> 7) & (NC - 1);
        int idx = (b * NC + c) * HH + n0 + tid;
        g_A[idx]  = (A0 * A1) * (A2 * A3);
        g_Bc[idx] = fmaf(A2 * A3, b01, b23);
    }

    // ---- coalesced g_a / g_b stores: 128 rows x 16 float4 ----
#pragma unroll
    for (int pass = 0; pass < 8; ++pass) {
        int r = pass * 16 + (tid >> 4);
        int c4 = tid & 15;
        size_t grow = (size_t)(m0 + r) * HH + n0 + c4 * 4;
        *(float4*)(g_a + grow) = *(float4*)(planeA + r * 68 + c4 * 4);
        *(float4*)(g_b + grow) = *(float4*)(planeB + r * 68 + c4 * 4);
    }
}

// ---------------- scan pass 2: combine chunks ----------------
__global__ __launch_bounds__(256)
void scan_chunk_combine(const float* __restrict__ h0) {
    int idx = blockIdx.x * blockDim.x + threadIdx.x;   // (b, h)
    int h = idx & (HH - 1);
    int b = idx >> 10;
    float carry = g_fn_scan(h0[b * HH + h]);
#pragma unroll
    for (int c = 0; c < NC; ++c) {
        int s = (b * NC + c) * HH + h;
        g_carry[s] = carry;
        carry = fmaf(g_A[s], carry, g_Bc[s]);
    }
}

// ---------------- scan pass 3: apply carries, write output ----------------
__global__ __launch_bounds__(256)
void scan_apply(float* __restrict__ out) {
    int idx = blockIdx.x * blockDim.x + threadIdx.x;   // (b, c, h)
    int h = idx & (HH - 1);
    int c = (idx >> 10) & (NC - 1);
    int b = idx >> 15;
    size_t base = ((size_t)(b * TT + c * CL)) * HH + h;
    float hc = g_carry[(b * NC + c) * HH + h];
#pragma unroll 8
    for (int i = 0; i < CL; ++i) {
        float a = g_a[base + (size_t)i * HH];
        float bb = g_b[base + (size_t)i * HH];
        hc = fmaf(a, hc, bb);
        out[base + (size_t)i * HH] = hc;
    }
}

extern "C" void kernel_launch(void* const* d_in, const int* in_sizes, int n_in,
                              void* d_out, int out_size) {
    const float* x  = (const float*)d_in[0];
    const float* h0 = (const float*)d_in[1];
    const float* Wz = (const float*)d_in[2];
    const float* bz = (const float*)d_in[3];
    const float* Wh = (const float*)d_in[4];
    const float* bh = (const float*)d_in[5];
    float* out = (float*)d_out;

    __half *x16, *wz, *wh;
    cudaGetSymbolAddress((void**)&x16, g_x16);
    cudaGetSymbolAddress((void**)&wz,  g_wz);
    cudaGetSymbolAddress((void**)&wh,  g_wh);

    cvt_kernel<<<(int)(((size_t)MTOT * II) / 1024), 256>>>(x, x16);
    cvt_kernel<<<(HH * II) / 1024, 256>>>(Wz, wz);
    cvt_kernel<<<(HH * II) / 1024, 256>>>(Wh, wh);

    cudaFuncSetAttribute(gemm_mma_kernel, cudaFuncAttributeMaxDynamicSharedMemorySize, SMEM_TOTAL);
    dim3 ggrid(HH / 64, MTOT / 128);   // x = n-block (16), y = m-block (256)
    gemm_mma_kernel<<<ggrid, 256, SMEM_TOTAL>>>(bz, bh);

    scan_chunk_combine<<<(BB * HH) / 256, 256>>>(h0);
    scan_apply<<<(BB * NC * HH) / 256, 256>>>(out);
}